// round 13
// baseline (speedup 1.0000x reference)
#include <cuda_runtime.h>
#include <cuda_bf16.h>
#include <cstdint>
#include <math.h>

// Problem dims (fixed by the dataset)
#define T_STEPS 512
#define B_SZ    64
#define D_SZ    256
#define H_SZ    256
#define ALPHA   0.9f

#define N_SCAN_CTAS   64
#define N_HELPERS     84
#define N_TILES       512   // 256 bm x 2 bn tiles of 128x128 (both GEMMs)

__device__ float g_xw[(size_t)T_STEPS * B_SZ * H_SZ];
__device__ int   g_stepcnt[T_STEPS];   // #scan CTAs that completed step s (odd s only)
__device__ int   g_xwcnt[256];         // per-bm xw tile completion (2 = ready)

// ---- f32x2 helpers (sm_103a packed fp32 FMA) --------------------------------
__device__ __forceinline__ unsigned long long pk2(float lo, float hi) {
    unsigned long long r;
    asm("mov.b64 %0, {%1, %2};" : "=l"(r) : "f"(lo), "f"(hi));
    return r;
}
__device__ __forceinline__ unsigned long long dup2(float a) {
    unsigned long long r;
    asm("mov.b64 %0, {%1, %1};" : "=l"(r) : "f"(a));
    return r;
}
__device__ __forceinline__ void fma2(unsigned long long& acc,
                                     unsigned long long a, unsigned long long b) {
    asm("fma.rn.f32x2 %0, %1, %2, %0;" : "+l"(acc) : "l"(a), "l"(b));
}
__device__ __forceinline__ float2 unpk(unsigned long long v) {
    float lo, hi;
    asm("mov.b64 {%0, %1}, %2;" : "=f"(lo), "=f"(hi) : "l"(v));
    return make_float2(lo, hi);
}

// ---- release/acquire flag ops ----------------------------------------------
__device__ __forceinline__ int ld_acq(const int* p) {
    int v;
    asm volatile("ld.acquire.gpu.global.s32 %0, [%1];" : "=r"(v) : "l"(p) : "memory");
    return v;
}
__device__ __forceinline__ void red_rel_add(int* p, int v) {
    asm volatile("red.release.gpu.global.add.s32 [%0], %1;" :: "l"(p), "r"(v) : "memory");
}
// L2-coherent load (bypass L1) for data produced concurrently in this grid
__device__ __forceinline__ float ld_cg(const float* p) {
    float v;
    asm volatile("ld.global.cg.f32 %0, [%1];" : "=f"(v) : "l"(p) : "memory");
    return v;
}

// ---------------------------------------------------------------------------
// One 128x128 GEMM tile body: C = A@Bm (+bias). BK=8, 256 threads, FFMA2.
// ---------------------------------------------------------------------------
__device__ __forceinline__ void gemm_tile(
    const float* __restrict__ A, const float* __restrict__ Bm,
    const float* __restrict__ bias, float* __restrict__ C,
    int bm, int bn, float* As, float* Bs)
{
    const int K = 256, N = 256;
    const int tid = threadIdx.x;
    const int tx = tid & 15;
    const int ty = tid >> 4;

    const int a_m = tid >> 1;
    const int a_k = (tid & 1) * 4;
    const int b_k = tid >> 5;
    const int b_n = (tid & 31) * 4;

    const float* Ap = A + (size_t)(bm + a_m) * K + a_k;
    const float* Bp = Bm + (size_t)b_k * N + bn + b_n;

    float4 af = *(const float4*)Ap;
    float4 bf = *(const float4*)Bp;

    unsigned long long acc2[8][4];
#pragma unroll
    for (int i = 0; i < 8; i++)
#pragma unroll
        for (int j = 0; j < 4; j++) acc2[i][j] = 0ull;

    int buf = 0;
    for (int kt = 0; kt < K; kt += 8) {
        As[(buf * 8 + a_k + 0) * 128 + a_m] = af.x;
        As[(buf * 8 + a_k + 1) * 128 + a_m] = af.y;
        As[(buf * 8 + a_k + 2) * 128 + a_m] = af.z;
        As[(buf * 8 + a_k + 3) * 128 + a_m] = af.w;
        *(float4*)&Bs[(buf * 8 + b_k) * 128 + b_n] = bf;
        __syncthreads();
        if (kt + 8 < K) {
            af = *(const float4*)(Ap + kt + 8);
            bf = *(const float4*)(Bp + (size_t)(kt + 8) * N);
        }
#pragma unroll
        for (int k = 0; k < 8; k++) {
            float4 a0 = *(const float4*)&As[(buf * 8 + k) * 128 + ty * 4];
            float4 a1 = *(const float4*)&As[(buf * 8 + k) * 128 + 64 + ty * 4];
            ulonglong2 bx0 = *(const ulonglong2*)&Bs[(buf * 8 + k) * 128 + tx * 4];
            ulonglong2 bx1 = *(const ulonglong2*)&Bs[(buf * 8 + k) * 128 + 64 + tx * 4];
            float av[8] = {a0.x, a0.y, a0.z, a0.w, a1.x, a1.y, a1.z, a1.w};
#pragma unroll
            for (int i = 0; i < 8; i++) {
                unsigned long long ad = dup2(av[i]);
                fma2(acc2[i][0], ad, bx0.x);
                fma2(acc2[i][1], ad, bx0.y);
                fma2(acc2[i][2], ad, bx1.x);
                fma2(acc2[i][3], ad, bx1.y);
            }
        }
        buf ^= 1;
    }

    float bv0[4], bv1[4];
#pragma unroll
    for (int j = 0; j < 4; j++) {
        bv0[j] = bias ? bias[bn + tx * 4 + j]      : 0.f;
        bv1[j] = bias ? bias[bn + 64 + tx * 4 + j] : 0.f;
    }

#pragma unroll
    for (int i = 0; i < 8; i++) {
        int r = bm + ((i < 4) ? (ty * 4 + i) : (64 + ty * 4 + (i - 4)));
        float2 p0 = unpk(acc2[i][0]), p1 = unpk(acc2[i][1]);
        float2 p2 = unpk(acc2[i][2]), p3 = unpk(acc2[i][3]);
        float4 o0, o1;
        o0.x = p0.x + bv0[0]; o0.y = p0.y + bv0[1];
        o0.z = p1.x + bv0[2]; o0.w = p1.y + bv0[3];
        o1.x = p2.x + bv1[0]; o1.y = p2.y + bv1[1];
        o1.z = p3.x + bv1[2]; o1.w = p3.y + bv1[3];
        *(float4*)&C[(size_t)r * N + bn + tx * 4]      = o0;
        *(float4*)&C[(size_t)r * N + bn + 64 + tx * 4] = o1;
    }
}

// ---------------------------------------------------------------------------
// Mega kernel. CTAs [0,64) = scan. CTAs [64,148) = helpers:
//   phase 1: xw tiles (bm-ascending), publish g_xwcnt[bm]
//   phase 2: preds tiles, gated on scan step counter (single address)
// ---------------------------------------------------------------------------
#define WREG_PAIRS 96    // 192 W_rec rows in registers
#define WSM_PAIRS  32    // 64 W_rec rows in smem (packed f32x2)

__global__ __launch_bounds__(256, 1) void mega_k(
    const float* __restrict__ inputs, const float* __restrict__ spike0,
    const float* __restrict__ v0,     const float* __restrict__ W_in,
    const float* __restrict__ W_rec,  const float* __restrict__ W_out,
    const float* __restrict__ bvec,
    float* __restrict__ spikes, float* __restrict__ preds,
    float* __restrict__ probs,  float* __restrict__ vT, float* __restrict__ sT,
    float* __restrict__ xw)
{
    extern __shared__ __align__(16) unsigned char dynsm[];

    if (blockIdx.x >= N_SCAN_CTAS) {
        // ================= helper CTA =================
        float* As = (float*)dynsm;
        float* Bs = As + 2 * 8 * 128;
        const int h = blockIdx.x - N_SCAN_CTAS;

        // Phase 1: xw = inputs @ W_in + b  (bm-ascending stride order)
        for (int i = h; i < N_TILES; i += N_HELPERS) {
            const int bm = i >> 1, bn = i & 1;
            gemm_tile(inputs, W_in, bvec, xw, bm * 128, bn * 128, As, Bs);
            __syncthreads();                      // all STGs done block-wide
            if (threadIdx.x == 0) red_rel_add(&g_xwcnt[bm], 1);
        }

        // Phase 2: preds = spikes[1:] @ W_out (gated on scan progress)
        const float* spk1 = spikes + (size_t)B_SZ * H_SZ;
        for (int i = h; i < N_TILES; i += N_HELPERS) {
            const int bm = i >> 1, bn = i & 1;
            const int need_step = 2 * bm + 1;     // odd; published by scan
            if (threadIdx.x == 0) {
                while (ld_acq(&g_stepcnt[need_step]) < N_SCAN_CTAS)
                    __nanosleep(512);
            }
            __syncthreads();                      // acquire visible block-wide
            gemm_tile(spk1, W_out, nullptr, preds, bm * 128, bn * 128, As, Bs);
            __syncthreads();
        }
        return;
    }

    // ================= scan CTA (R6 design + xw gating) =================
    unsigned long long* w2 = (unsigned long long*)dynsm;     // [WSM_PAIRS*256]
    float* sbuf = (float*)(w2 + WSM_PAIRS * 256);            // [2][256]

    const int t   = threadIdx.x;   // output column
    const int row = blockIdx.x;    // batch row

#pragma unroll
    for (int j = 0; j < WSM_PAIRS; j++)
        w2[j * 256 + t] = pk2(W_rec[(size_t)(2 * WREG_PAIRS + 2 * j) * 256 + t],
                              W_rec[(size_t)(2 * WREG_PAIRS + 2 * j + 1) * 256 + t]);

    unsigned long long wpk[WREG_PAIRS];
#pragma unroll
    for (int j = 0; j < WREG_PAIRS; j++)
        wpk[j] = pk2(W_rec[(size_t)(2 * j) * 256 + t],
                     W_rec[(size_t)(2 * j + 1) * 256 + t]);

    const float s0 = spike0[row * 256 + t];
    sbuf[t] = s0;
    spikes[(size_t)row * 256 + t] = s0;          // spikes[0] = spike0
    float v = v0[row * 256 + t];
    float prob = s0;

    const float* xwp = xw + (size_t)row * 256 + t;

    // Wait for xw bm=0 (exact check; all threads poll same address, converged)
    while (ld_acq(&g_xwcnt[0]) < 2) __nanosleep(128);
    float xnext = ld_cg(xwp);    // L2-coherent: xw written by peer CTAs

    __syncthreads();

    int cur = 0;
    for (int step = 0; step < T_STEPS; step++) {
        const float xval = xnext;
        if (step + 1 < T_STEPS) {
            const int bm = (step + 1) >> 1;
            if (((step + 1) & 1) == 0) {          // entering a new bm tile
                while (ld_acq(&g_xwcnt[bm]) < 2) __nanosleep(128);
            }
            xnext = ld_cg(xwp + (size_t)(step + 1) * (B_SZ * H_SZ));
        }

        unsigned long long a4[4] = {0ull, 0ull, 0ull, 0ull};

        const ulonglong2* sp = (const ulonglong2*)&sbuf[cur * 256];
#pragma unroll
        for (int q = 0; q < WREG_PAIRS / 2; q++) {
            ulonglong2 sv = sp[q];
            fma2(a4[(2 * q) & 3],     wpk[2 * q],     sv.x);
            fma2(a4[(2 * q + 1) & 3], wpk[2 * q + 1], sv.y);
        }
        const ulonglong2* sp2 = (const ulonglong2*)&sbuf[cur * 256 + 2 * WREG_PAIRS];
#pragma unroll
        for (int q = 0; q < WSM_PAIRS / 2; q++) {
            ulonglong2 sv = sp2[q];
            fma2(a4[0], w2[(2 * q) * 256 + t],     sv.x);
            fma2(a4[1], w2[(2 * q + 1) * 256 + t], sv.y);
        }

        float2 q0 = unpk(a4[0]), q1 = unpk(a4[1]), q2 = unpk(a4[2]), q3 = unpk(a4[3]);
        float acc = ((q0.x + q0.y) + (q1.x + q1.y)) + ((q2.x + q2.y) + (q3.x + q3.y));

        v = ALPHA * v + xval + acc;
        prob = __fdividef(1.0f, 1.0f + __expf(-v));

        const size_t off = ((size_t)step * B_SZ + row) * 256 + t;
        probs[off] = prob;                        // probs[step]
        spikes[off + (size_t)B_SZ * 256] = prob;  // spikes[step+1]

        const int nxt = cur ^ 1;
        sbuf[nxt * 256 + t] = prob;
        __syncthreads();   // all lanes' STGs ordered before publish (HB chain)
        if (t == 0 && (step & 1)) red_rel_add(&g_stepcnt[step], 1);
        cur = nxt;
    }

    vT[row * 256 + t] = v;
    sT[row * 256 + t] = prob;
}

// ---------------------------------------------------------------------------
// Launch: memset flags -> ONE persistent mega kernel. Capture-safe.
// ---------------------------------------------------------------------------
extern "C" void kernel_launch(void* const* d_in, const int* in_sizes, int n_in,
                              void* d_out, int out_size)
{
    const float* inputs = (const float*)d_in[0];  // [512,64,256]
    const float* spike0 = (const float*)d_in[1];  // [64,256]
    const float* v0     = (const float*)d_in[2];  // [64,256]
    const float* W_in   = (const float*)d_in[3];  // [256,256]
    const float* W_rec  = (const float*)d_in[4];  // [256,256]
    const float* W_out  = (const float*)d_in[5];  // [256,256]
    const float* bvec   = (const float*)d_in[6];  // [256]

    float* out = (float*)d_out;
    float* spikes = out;
    float* preds  = out + (size_t)513 * B_SZ * H_SZ;
    float* probs  = preds + (size_t)T_STEPS * B_SZ * H_SZ;
    float* vT     = probs + (size_t)T_STEPS * B_SZ * H_SZ;
    float* sT     = vT + (size_t)B_SZ * H_SZ;

    float* xw = nullptr;
    cudaGetSymbolAddress((void**)&xw, g_xw);
    int* stepcnt = nullptr;
    cudaGetSymbolAddress((void**)&stepcnt, g_stepcnt);
    int* xwcnt = nullptr;
    cudaGetSymbolAddress((void**)&xwcnt, g_xwcnt);

    cudaMemsetAsync(stepcnt, 0, T_STEPS * sizeof(int));
    cudaMemsetAsync(xwcnt, 0, 256 * sizeof(int));

    const size_t smem = (size_t)WSM_PAIRS * 256 * 8 + 2 * 256 * sizeof(float);
    cudaFuncSetAttribute(mega_k, cudaFuncAttributeMaxDynamicSharedMemorySize,
                         (int)smem);

    mega_k<<<N_SCAN_CTAS + N_HELPERS, 256, smem>>>(
        inputs, spike0, v0, W_in, W_rec, W_out, bvec,
        spikes, preds, probs, vT, sT, xw);
}

// round 14
// speedup vs baseline: 1.1933x; 1.1933x over previous
#include <cuda_runtime.h>
#include <cuda_bf16.h>
#include <cstdint>
#include <math.h>

// Problem dims (fixed by the dataset)
#define T_STEPS 512
#define B_SZ    64
#define D_SZ    256
#define H_SZ    256
#define ALPHA   0.9f

#define N_SCAN_CTAS   64
#define N_HELPERS     84
#define N_TILES       512   // preds: 256 bm x 2 bn, tiles of 128x128

__device__ float g_xw[(size_t)T_STEPS * B_SZ * H_SZ];
__device__ int   g_stepcnt[T_STEPS];   // #scan CTAs that completed step s (odd only)

// ---- f32x2 helpers (sm_103a packed fp32 FMA) --------------------------------
__device__ __forceinline__ unsigned long long pk2(float lo, float hi) {
    unsigned long long r;
    asm("mov.b64 %0, {%1, %2};" : "=l"(r) : "f"(lo), "f"(hi));
    return r;
}
__device__ __forceinline__ unsigned long long dup2(float a) {
    unsigned long long r;
    asm("mov.b64 %0, {%1, %1};" : "=l"(r) : "f"(a));
    return r;
}
__device__ __forceinline__ void fma2(unsigned long long& acc,
                                     unsigned long long a, unsigned long long b) {
    asm("fma.rn.f32x2 %0, %1, %2, %0;" : "+l"(acc) : "l"(a), "l"(b));
}
__device__ __forceinline__ float2 unpk(unsigned long long v) {
    float lo, hi;
    asm("mov.b64 {%0, %1}, %2;" : "=f"(lo), "=f"(hi) : "l"(v));
    return make_float2(lo, hi);
}

// ---- release/acquire flag ops ----------------------------------------------
__device__ __forceinline__ int ld_acq(const int* p) {
    int v;
    asm volatile("ld.acquire.gpu.global.s32 %0, [%1];" : "=r"(v) : "l"(p) : "memory");
    return v;
}
__device__ __forceinline__ void red_rel_add(int* p, int v) {
    asm volatile("red.release.gpu.global.add.s32 [%0], %1;" :: "l"(p), "r"(v) : "memory");
}

// ---------------------------------------------------------------------------
// One 128x128 GEMM tile body: C = A@Bm (+bias). BK=8, 256 threads, FFMA2.
// ---------------------------------------------------------------------------
__device__ __forceinline__ void gemm_tile(
    const float* __restrict__ A, const float* __restrict__ Bm,
    const float* __restrict__ bias, float* __restrict__ C,
    int bm, int bn, float* As, float* Bs)
{
    const int K = 256, N = 256;
    const int tid = threadIdx.x;
    const int tx = tid & 15;
    const int ty = tid >> 4;

    const int a_m = tid >> 1;
    const int a_k = (tid & 1) * 4;
    const int b_k = tid >> 5;
    const int b_n = (tid & 31) * 4;

    const float* Ap = A + (size_t)(bm + a_m) * K + a_k;
    const float* Bp = Bm + (size_t)b_k * N + bn + b_n;

    float4 af = *(const float4*)Ap;
    float4 bf = *(const float4*)Bp;

    unsigned long long acc2[8][4];
#pragma unroll
    for (int i = 0; i < 8; i++)
#pragma unroll
        for (int j = 0; j < 4; j++) acc2[i][j] = 0ull;

    int buf = 0;
    for (int kt = 0; kt < K; kt += 8) {
        As[(buf * 8 + a_k + 0) * 128 + a_m] = af.x;
        As[(buf * 8 + a_k + 1) * 128 + a_m] = af.y;
        As[(buf * 8 + a_k + 2) * 128 + a_m] = af.z;
        As[(buf * 8 + a_k + 3) * 128 + a_m] = af.w;
        *(float4*)&Bs[(buf * 8 + b_k) * 128 + b_n] = bf;
        __syncthreads();
        if (kt + 8 < K) {
            af = *(const float4*)(Ap + kt + 8);
            bf = *(const float4*)(Bp + (size_t)(kt + 8) * N);
        }
#pragma unroll
        for (int k = 0; k < 8; k++) {
            float4 a0 = *(const float4*)&As[(buf * 8 + k) * 128 + ty * 4];
            float4 a1 = *(const float4*)&As[(buf * 8 + k) * 128 + 64 + ty * 4];
            ulonglong2 bx0 = *(const ulonglong2*)&Bs[(buf * 8 + k) * 128 + tx * 4];
            ulonglong2 bx1 = *(const ulonglong2*)&Bs[(buf * 8 + k) * 128 + 64 + tx * 4];
            float av[8] = {a0.x, a0.y, a0.z, a0.w, a1.x, a1.y, a1.z, a1.w};
#pragma unroll
            for (int i = 0; i < 8; i++) {
                unsigned long long ad = dup2(av[i]);
                fma2(acc2[i][0], ad, bx0.x);
                fma2(acc2[i][1], ad, bx0.y);
                fma2(acc2[i][2], ad, bx1.x);
                fma2(acc2[i][3], ad, bx1.y);
            }
        }
        buf ^= 1;
    }

    float bv0[4], bv1[4];
#pragma unroll
    for (int j = 0; j < 4; j++) {
        bv0[j] = bias ? bias[bn + tx * 4 + j]      : 0.f;
        bv1[j] = bias ? bias[bn + 64 + tx * 4 + j] : 0.f;
    }

#pragma unroll
    for (int i = 0; i < 8; i++) {
        int r = bm + ((i < 4) ? (ty * 4 + i) : (64 + ty * 4 + (i - 4)));
        float2 p0 = unpk(acc2[i][0]), p1 = unpk(acc2[i][1]);
        float2 p2 = unpk(acc2[i][2]), p3 = unpk(acc2[i][3]);
        float4 o0, o1;
        o0.x = p0.x + bv0[0]; o0.y = p0.y + bv0[1];
        o0.z = p1.x + bv0[2]; o0.w = p1.y + bv0[3];
        o1.x = p2.x + bv1[0]; o1.y = p2.y + bv1[1];
        o1.z = p3.x + bv1[2]; o1.w = p3.y + bv1[3];
        *(float4*)&C[(size_t)r * N + bn + tx * 4]      = o0;
        *(float4*)&C[(size_t)r * N + bn + 64 + tx * 4] = o1;
    }
}

// Standalone full-chip GEMM for xw (proven config)
__global__ __launch_bounds__(256) void sgemm_k(
    const float* __restrict__ A, const float* __restrict__ Bm,
    const float* __restrict__ bias, float* __restrict__ C)
{
    __shared__ float As[2 * 8 * 128];
    __shared__ float Bs[2 * 8 * 128];
    gemm_tile(A, Bm, bias, C, blockIdx.x * 128, blockIdx.y * 128, As, Bs);
}

// ---------------------------------------------------------------------------
// Mega kernel: CTAs [0,64) = scan; CTAs [64,148) = preds helpers.
// Scan: W split 88 reg-pairs / 40 smem-pairs (frees ~28 regs for ptxas to
// pipeline s-vector LDS). Publishes odd-step completion via red.release.
// ---------------------------------------------------------------------------
#define WREG_PAIRS 88    // 176 W_rec rows in registers
#define WSM_PAIRS  40    // 80 W_rec rows in smem (packed f32x2)

__global__ __launch_bounds__(256, 1) void mega_k(
    const float* __restrict__ spike0, const float* __restrict__ v0,
    const float* __restrict__ W_rec,  const float* __restrict__ W_out,
    float* __restrict__ spikes, float* __restrict__ preds,
    float* __restrict__ probs,  float* __restrict__ vT, float* __restrict__ sT,
    const float* __restrict__ xw)
{
    extern __shared__ __align__(16) unsigned char dynsm[];

    if (blockIdx.x >= N_SCAN_CTAS) {
        // ================= preds helper =================
        float* As = (float*)dynsm;
        float* Bs = As + 2 * 8 * 128;
        const int h = blockIdx.x - N_SCAN_CTAS;
        const float* spk1 = spikes + (size_t)B_SZ * H_SZ;   // spikes[1:]

        for (int i = h; i < N_TILES; i += N_HELPERS) {
            const int bm = i >> 1, bn = i & 1;
            const int need_step = 2 * bm + 1;     // odd; published by scan
            if (threadIdx.x == 0) {
                while (ld_acq(&g_stepcnt[need_step]) < N_SCAN_CTAS)
                    __nanosleep(512);
            }
            __syncthreads();                      // acquire visible block-wide
            gemm_tile(spk1, W_out, nullptr, preds, bm * 128, bn * 128, As, Bs);
            __syncthreads();
        }
        return;
    }

    // ================= scan CTA =================
    unsigned long long* w2 = (unsigned long long*)dynsm;     // [WSM_PAIRS*256]
    float* sbuf = (float*)(w2 + WSM_PAIRS * 256);            // [2][256]

    const int t   = threadIdx.x;   // output column
    const int row = blockIdx.x;    // batch row

#pragma unroll
    for (int j = 0; j < WSM_PAIRS; j++)
        w2[j * 256 + t] = pk2(W_rec[(size_t)(2 * WREG_PAIRS + 2 * j) * 256 + t],
                              W_rec[(size_t)(2 * WREG_PAIRS + 2 * j + 1) * 256 + t]);

    unsigned long long wpk[WREG_PAIRS];
#pragma unroll
    for (int j = 0; j < WREG_PAIRS; j++)
        wpk[j] = pk2(W_rec[(size_t)(2 * j) * 256 + t],
                     W_rec[(size_t)(2 * j + 1) * 256 + t]);

    const float s0 = spike0[row * 256 + t];
    sbuf[t] = s0;
    spikes[(size_t)row * 256 + t] = s0;          // spikes[0] = spike0
    float v = v0[row * 256 + t];
    float prob = s0;

    const float* xwp = xw + (size_t)row * 256 + t;
    float xnext = __ldg(xwp);

    __syncthreads();

    int cur = 0;
    for (int step = 0; step < T_STEPS; step++) {
        const float xval = xnext;
        if (step + 1 < T_STEPS)
            xnext = __ldg(xwp + (size_t)(step + 1) * (B_SZ * H_SZ));

        unsigned long long a4[4] = {0ull, 0ull, 0ull, 0ull};

        const ulonglong2* sp = (const ulonglong2*)&sbuf[cur * 256];
#pragma unroll
        for (int q = 0; q < WREG_PAIRS / 2; q++) {
            ulonglong2 sv = sp[q];
            fma2(a4[(2 * q) & 3],     wpk[2 * q],     sv.x);
            fma2(a4[(2 * q + 1) & 3], wpk[2 * q + 1], sv.y);
        }
        const ulonglong2* sp2 = (const ulonglong2*)&sbuf[cur * 256 + 2 * WREG_PAIRS];
#pragma unroll
        for (int q = 0; q < WSM_PAIRS / 2; q++) {
            ulonglong2 sv = sp2[q];
            fma2(a4[0], w2[(2 * q) * 256 + t],     sv.x);
            fma2(a4[1], w2[(2 * q + 1) * 256 + t], sv.y);
        }

        float2 q0 = unpk(a4[0]), q1 = unpk(a4[1]), q2 = unpk(a4[2]), q3 = unpk(a4[3]);
        float acc = ((q0.x + q0.y) + (q1.x + q1.y)) + ((q2.x + q2.y) + (q3.x + q3.y));

        v = ALPHA * v + xval + acc;
        prob = __fdividef(1.0f, 1.0f + __expf(-v));

        const size_t off = ((size_t)step * B_SZ + row) * 256 + t;
        probs[off] = prob;                        // probs[step]
        spikes[off + (size_t)B_SZ * 256] = prob;  // spikes[step+1]

        const int nxt = cur ^ 1;
        sbuf[nxt * 256 + t] = prob;
        __syncthreads();   // all lanes' STGs ordered before publish (HB chain)
        if (t == 0 && (step & 1)) red_rel_add(&g_stepcnt[step], 1);
        cur = nxt;
    }

    vT[row * 256 + t] = v;
    sT[row * 256 + t] = prob;
}

// ---------------------------------------------------------------------------
// Launch: memset flags -> sgemm(xw) -> mega(scan + preds helpers).
// ---------------------------------------------------------------------------
extern "C" void kernel_launch(void* const* d_in, const int* in_sizes, int n_in,
                              void* d_out, int out_size)
{
    const float* inputs = (const float*)d_in[0];  // [512,64,256]
    const float* spike0 = (const float*)d_in[1];  // [64,256]
    const float* v0     = (const float*)d_in[2];  // [64,256]
    const float* W_in   = (const float*)d_in[3];  // [256,256]
    const float* W_rec  = (const float*)d_in[4];  // [256,256]
    const float* W_out  = (const float*)d_in[5];  // [256,256]
    const float* bvec   = (const float*)d_in[6];  // [256]

    float* out = (float*)d_out;
    float* spikes = out;
    float* preds  = out + (size_t)513 * B_SZ * H_SZ;
    float* probs  = preds + (size_t)T_STEPS * B_SZ * H_SZ;
    float* vT     = probs + (size_t)T_STEPS * B_SZ * H_SZ;
    float* sT     = vT + (size_t)B_SZ * H_SZ;

    float* xw = nullptr;
    cudaGetSymbolAddress((void**)&xw, g_xw);
    int* stepcnt = nullptr;
    cudaGetSymbolAddress((void**)&stepcnt, g_stepcnt);

    cudaMemsetAsync(stepcnt, 0, T_STEPS * sizeof(int));

    const size_t smem = (size_t)WSM_PAIRS * 256 * 8 + 2 * 256 * sizeof(float);
    cudaFuncSetAttribute(mega_k, cudaFuncAttributeMaxDynamicSharedMemorySize,
                         (int)smem);

    dim3 gemm_grid((T_STEPS * B_SZ) / 128, H_SZ / 128);  // (256, 2)

    // 1) xw = inputs @ W_in + b (full chip)
    sgemm_k<<<gemm_grid, 256>>>(inputs, W_in, bvec, xw);

    // 2) scan + overlapped preds GEMM
    mega_k<<<N_SCAN_CTAS + N_HELPERS, 256, smem>>>(
        spike0, v0, W_rec, W_out, spikes, preds, probs, vT, sT, xw);
}

// round 15
// speedup vs baseline: 1.2135x; 1.0169x over previous
#include <cuda_runtime.h>
#include <cuda_bf16.h>
#include <cstdint>
#include <math.h>

// Problem dims (fixed by the dataset)
#define T_STEPS 512
#define B_SZ    64
#define D_SZ    256
#define H_SZ    256
#define ALPHA   0.9f

#define N_SCAN_CTAS   64
#define N_HELPERS     84
#define N_TILES       512   // preds: 256 bm x 2 bn, tiles of 128x128

__device__ float g_xw[(size_t)T_STEPS * B_SZ * H_SZ];
__device__ int   g_stepcnt[T_STEPS];   // #scan CTAs that completed step s (odd only)

// ---- f32x2 helpers (sm_103a packed fp32 FMA) --------------------------------
__device__ __forceinline__ unsigned long long pk2(float lo, float hi) {
    unsigned long long r;
    asm("mov.b64 %0, {%1, %2};" : "=l"(r) : "f"(lo), "f"(hi));
    return r;
}
__device__ __forceinline__ unsigned long long dup2(float a) {
    unsigned long long r;
    asm("mov.b64 %0, {%1, %1};" : "=l"(r) : "f"(a));
    return r;
}
__device__ __forceinline__ void fma2(unsigned long long& acc,
                                     unsigned long long a, unsigned long long b) {
    asm("fma.rn.f32x2 %0, %1, %2, %0;" : "+l"(acc) : "l"(a), "l"(b));
}
__device__ __forceinline__ float2 unpk(unsigned long long v) {
    float lo, hi;
    asm("mov.b64 {%0, %1}, %2;" : "=f"(lo), "=f"(hi) : "l"(v));
    return make_float2(lo, hi);
}

// ---- release/acquire flag ops ----------------------------------------------
__device__ __forceinline__ int ld_acq(const int* p) {
    int v;
    asm volatile("ld.acquire.gpu.global.s32 %0, [%1];" : "=r"(v) : "l"(p) : "memory");
    return v;
}
__device__ __forceinline__ void red_rel_add(int* p, int v) {
    asm volatile("red.release.gpu.global.add.s32 [%0], %1;" :: "l"(p), "r"(v) : "memory");
}

// ---------------------------------------------------------------------------
// One 128x128 GEMM tile body: C = A@Bm (+bias). BK=8, 256 threads, FFMA2.
// ---------------------------------------------------------------------------
__device__ __forceinline__ void gemm_tile(
    const float* __restrict__ A, const float* __restrict__ Bm,
    const float* __restrict__ bias, float* __restrict__ C,
    int bm, int bn, float* As, float* Bs)
{
    const int K = 256, N = 256;
    const int tid = threadIdx.x;
    const int tx = tid & 15;
    const int ty = tid >> 4;

    const int a_m = tid >> 1;
    const int a_k = (tid & 1) * 4;
    const int b_k = tid >> 5;
    const int b_n = (tid & 31) * 4;

    const float* Ap = A + (size_t)(bm + a_m) * K + a_k;
    const float* Bp = Bm + (size_t)b_k * N + bn + b_n;

    float4 af = *(const float4*)Ap;
    float4 bf = *(const float4*)Bp;

    unsigned long long acc2[8][4];
#pragma unroll
    for (int i = 0; i < 8; i++)
#pragma unroll
        for (int j = 0; j < 4; j++) acc2[i][j] = 0ull;

    int buf = 0;
    for (int kt = 0; kt < K; kt += 8) {
        As[(buf * 8 + a_k + 0) * 128 + a_m] = af.x;
        As[(buf * 8 + a_k + 1) * 128 + a_m] = af.y;
        As[(buf * 8 + a_k + 2) * 128 + a_m] = af.z;
        As[(buf * 8 + a_k + 3) * 128 + a_m] = af.w;
        *(float4*)&Bs[(buf * 8 + b_k) * 128 + b_n] = bf;
        __syncthreads();
        if (kt + 8 < K) {
            af = *(const float4*)(Ap + kt + 8);
            bf = *(const float4*)(Bp + (size_t)(kt + 8) * N);
        }
#pragma unroll
        for (int k = 0; k < 8; k++) {
            float4 a0 = *(const float4*)&As[(buf * 8 + k) * 128 + ty * 4];
            float4 a1 = *(const float4*)&As[(buf * 8 + k) * 128 + 64 + ty * 4];
            ulonglong2 bx0 = *(const ulonglong2*)&Bs[(buf * 8 + k) * 128 + tx * 4];
            ulonglong2 bx1 = *(const ulonglong2*)&Bs[(buf * 8 + k) * 128 + 64 + tx * 4];
            float av[8] = {a0.x, a0.y, a0.z, a0.w, a1.x, a1.y, a1.z, a1.w};
#pragma unroll
            for (int i = 0; i < 8; i++) {
                unsigned long long ad = dup2(av[i]);
                fma2(acc2[i][0], ad, bx0.x);
                fma2(acc2[i][1], ad, bx0.y);
                fma2(acc2[i][2], ad, bx1.x);
                fma2(acc2[i][3], ad, bx1.y);
            }
        }
        buf ^= 1;
    }

    float bv0[4], bv1[4];
#pragma unroll
    for (int j = 0; j < 4; j++) {
        bv0[j] = bias ? bias[bn + tx * 4 + j]      : 0.f;
        bv1[j] = bias ? bias[bn + 64 + tx * 4 + j] : 0.f;
    }

#pragma unroll
    for (int i = 0; i < 8; i++) {
        int r = bm + ((i < 4) ? (ty * 4 + i) : (64 + ty * 4 + (i - 4)));
        float2 p0 = unpk(acc2[i][0]), p1 = unpk(acc2[i][1]);
        float2 p2 = unpk(acc2[i][2]), p3 = unpk(acc2[i][3]);
        float4 o0, o1;
        o0.x = p0.x + bv0[0]; o0.y = p0.y + bv0[1];
        o0.z = p1.x + bv0[2]; o0.w = p1.y + bv0[3];
        o1.x = p2.x + bv1[0]; o1.y = p2.y + bv1[1];
        o1.z = p3.x + bv1[2]; o1.w = p3.y + bv1[3];
        *(float4*)&C[(size_t)r * N + bn + tx * 4]      = o0;
        *(float4*)&C[(size_t)r * N + bn + 64 + tx * 4] = o1;
    }
}

// Standalone full-chip GEMM for xw (proven config)
__global__ __launch_bounds__(256) void sgemm_k(
    const float* __restrict__ A, const float* __restrict__ Bm,
    const float* __restrict__ bias, float* __restrict__ C)
{
    __shared__ float As[2 * 8 * 128];
    __shared__ float Bs[2 * 8 * 128];
    gemm_tile(A, Bm, bias, C, blockIdx.x * 128, blockIdx.y * 128, As, Bs);
}

// ---------------------------------------------------------------------------
// Mega kernel: CTAs [0,64) = scan; CTAs [64,148) = preds helpers.
// Scan: 96 reg-pairs + 32 smem-pairs; smem W packed as ulonglong2 (LDS.128).
// ---------------------------------------------------------------------------
#define WREG_PAIRS 96    // 192 W_rec rows in registers
#define WSM_PAIRS  32    // 64 W_rec rows in smem (16 ulonglong2 per thread)
#define WSM_VECS   (WSM_PAIRS / 2)   // 16

__global__ __launch_bounds__(256, 1) void mega_k(
    const float* __restrict__ spike0, const float* __restrict__ v0,
    const float* __restrict__ W_rec,  const float* __restrict__ W_out,
    float* __restrict__ spikes, float* __restrict__ preds,
    float* __restrict__ probs,  float* __restrict__ vT, float* __restrict__ sT,
    const float* __restrict__ xw)
{
    extern __shared__ __align__(16) unsigned char dynsm[];

    if (blockIdx.x >= N_SCAN_CTAS) {
        // ================= preds helper =================
        float* As = (float*)dynsm;
        float* Bs = As + 2 * 8 * 128;
        const int h = blockIdx.x - N_SCAN_CTAS;
        const float* spk1 = spikes + (size_t)B_SZ * H_SZ;   // spikes[1:]

        for (int i = h; i < N_TILES; i += N_HELPERS) {
            const int bm = i >> 1, bn = i & 1;
            const int need_step = 2 * bm + 1;     // odd; published by scan
            if (threadIdx.x == 0) {
                while (ld_acq(&g_stepcnt[need_step]) < N_SCAN_CTAS)
                    __nanosleep(512);
            }
            __syncthreads();                      // acquire visible block-wide
            gemm_tile(spk1, W_out, nullptr, preds, bm * 128, bn * 128, As, Bs);
            __syncthreads();
        }
        return;
    }

    // ================= scan CTA =================
    ulonglong2* w4 = (ulonglong2*)dynsm;                     // [WSM_VECS*256]
    float* sbuf = (float*)(w4 + WSM_VECS * 256);             // [2][256]

    const int t   = threadIdx.x;   // output column
    const int row = blockIdx.x;    // batch row

    // Stage smem W as packed ulonglong2: vec q covers k rows 192+4q..195+4q
#pragma unroll
    for (int q = 0; q < WSM_VECS; q++) {
        const int kb = 2 * WREG_PAIRS + 4 * q;
        ulonglong2 wv;
        wv.x = pk2(W_rec[(size_t)(kb + 0) * 256 + t], W_rec[(size_t)(kb + 1) * 256 + t]);
        wv.y = pk2(W_rec[(size_t)(kb + 2) * 256 + t], W_rec[(size_t)(kb + 3) * 256 + t]);
        w4[q * 256 + t] = wv;
    }

    // Register-resident W pairs: rows [0,192)
    unsigned long long wpk[WREG_PAIRS];
#pragma unroll
    for (int j = 0; j < WREG_PAIRS; j++)
        wpk[j] = pk2(W_rec[(size_t)(2 * j) * 256 + t],
                     W_rec[(size_t)(2 * j + 1) * 256 + t]);

    const float s0 = spike0[row * 256 + t];
    sbuf[t] = s0;
    spikes[(size_t)row * 256 + t] = s0;          // spikes[0] = spike0
    float v = v0[row * 256 + t];
    float prob = s0;

    const float* xwp = xw + (size_t)row * 256 + t;
    float xnext = __ldg(xwp);

    __syncthreads();

    int cur = 0;
    for (int step = 0; step < T_STEPS; step++) {
        const float xval = xnext;
        if (step + 1 < T_STEPS)
            xnext = __ldg(xwp + (size_t)(step + 1) * (B_SZ * H_SZ));

        unsigned long long a4[4] = {0ull, 0ull, 0ull, 0ull};

        // Register part: k in [0,192): 48 LDS.128 (s) + 96 FFMA2
        const ulonglong2* sp = (const ulonglong2*)&sbuf[cur * 256];
#pragma unroll
        for (int q = 0; q < WREG_PAIRS / 2; q++) {
            ulonglong2 sv = sp[q];
            fma2(a4[(2 * q) & 3],     wpk[2 * q],     sv.x);
            fma2(a4[(2 * q + 1) & 3], wpk[2 * q + 1], sv.y);
        }
        // Smem part: k in [192,256): 16 LDS.128 (s) + 16 LDS.128 (W) + 32 FFMA2
        const ulonglong2* sp2 = (const ulonglong2*)&sbuf[cur * 256 + 2 * WREG_PAIRS];
#pragma unroll
        for (int q = 0; q < WSM_VECS; q++) {
            ulonglong2 sv = sp2[q];
            ulonglong2 wv = w4[q * 256 + t];
            fma2(a4[0], wv.x, sv.x);
            fma2(a4[1], wv.y, sv.y);
        }

        float2 q0 = unpk(a4[0]), q1 = unpk(a4[1]), q2 = unpk(a4[2]), q3 = unpk(a4[3]);
        float acc = ((q0.x + q0.y) + (q1.x + q1.y)) + ((q2.x + q2.y) + (q3.x + q3.y));

        v = ALPHA * v + xval + acc;
        prob = __fdividef(1.0f, 1.0f + __expf(-v));

        const size_t off = ((size_t)step * B_SZ + row) * 256 + t;
        probs[off] = prob;                        // probs[step]
        spikes[off + (size_t)B_SZ * 256] = prob;  // spikes[step+1]

        const int nxt = cur ^ 1;
        sbuf[nxt * 256 + t] = prob;
        __syncthreads();   // all lanes' STGs ordered before publish (HB chain)
        if (t == 0 && (step & 1)) red_rel_add(&g_stepcnt[step], 1);
        cur = nxt;
    }

    vT[row * 256 + t] = v;
    sT[row * 256 + t] = prob;
}

// ---------------------------------------------------------------------------
// Launch: memset flags -> sgemm(xw) -> mega(scan + preds helpers).
// ---------------------------------------------------------------------------
extern "C" void kernel_launch(void* const* d_in, const int* in_sizes, int n_in,
                              void* d_out, int out_size)
{
    const float* inputs = (const float*)d_in[0];  // [512,64,256]
    const float* spike0 = (const float*)d_in[1];  // [64,256]
    const float* v0     = (const float*)d_in[2];  // [64,256]
    const float* W_in   = (const float*)d_in[3];  // [256,256]
    const float* W_rec  = (const float*)d_in[4];  // [256,256]
    const float* W_out  = (const float*)d_in[5];  // [256,256]
    const float* bvec   = (const float*)d_in[6];  // [256]

    float* out = (float*)d_out;
    float* spikes = out;
    float* preds  = out + (size_t)513 * B_SZ * H_SZ;
    float* probs  = preds + (size_t)T_STEPS * B_SZ * H_SZ;
    float* vT     = probs + (size_t)T_STEPS * B_SZ * H_SZ;
    float* sT     = vT + (size_t)B_SZ * H_SZ;

    float* xw = nullptr;
    cudaGetSymbolAddress((void**)&xw, g_xw);
    int* stepcnt = nullptr;
    cudaGetSymbolAddress((void**)&stepcnt, g_stepcnt);

    cudaMemsetAsync(stepcnt, 0, T_STEPS * sizeof(int));

    const size_t smem = (size_t)WSM_VECS * 256 * sizeof(ulonglong2)
                      + 2 * 256 * sizeof(float);
    cudaFuncSetAttribute(mega_k, cudaFuncAttributeMaxDynamicSharedMemorySize,
                         (int)smem);

    dim3 gemm_grid((T_STEPS * B_SZ) / 128, H_SZ / 128);  // (256, 2)

    // 1) xw = inputs @ W_in + b (full chip)
    sgemm_k<<<gemm_grid, 256>>>(inputs, W_in, bvec, xw);

    // 2) scan + overlapped preds GEMM
    mega_k<<<N_SCAN_CTAS + N_HELPERS, 256, smem>>>(
        spike0, v0, W_rec, W_out, spikes, preds, probs, vT, sT, xw);
}